// round 10
// baseline (speedup 1.0000x reference)
#include <cuda_runtime.h>
#include <math.h>
#include <stdint.h>

typedef unsigned long long u64;

// ---------------- scratch (device globals; no allocation allowed) ----------
__device__ float g_xg  [16u*2048u*512u];   // precomputed input gates [B,S,4H]
__device__ float g_lstm[16u*2048u*128u];   // lstm hidden states [B,S,H]
__device__ float g_ctx [16u*2048u*128u];   // attention context [B,S,H]
__device__ float g_ha  [32768u*132u];      // MLP ping buffer (stride 132)
__device__ float g_hb  [32768u*132u];      // MLP pong buffer

__device__ __forceinline__ float sigf(float x) {
    return __fdividef(1.f, 1.f + __expf(-x));
}
__device__ __forceinline__ float tanh_fast(float x) {
    return fmaf(2.f, sigf(2.f * x), -1.f);
}

// packed f32x2 helpers ------------------------------------------------------
__device__ __forceinline__ void fma2(u64& c, u64 a, u64 b) {
    asm("fma.rn.f32x2 %0, %1, %2, %0;" : "+l"(c) : "l"(a), "l"(b));
}
__device__ __forceinline__ float2 upk(u64 v) {
    unsigned lo, hi;
    asm("mov.b64 {%0, %1}, %2;" : "=r"(lo), "=r"(hi) : "l"(v));
    return make_float2(__uint_as_float(lo), __uint_as_float(hi));
}
__device__ __forceinline__ float hsum2(u64 v) { float2 f = upk(v); return f.x + f.y; }

// tf32 helpers ---------------------------------------------------------------
__device__ __forceinline__ unsigned tf32of(float f) {
    unsigned u; asm("cvt.rna.tf32.f32 %0, %1;" : "=r"(u) : "f"(f)); return u;
}
__device__ __forceinline__ void mma_tf32(float* c, const unsigned* a,
                                         unsigned b0, unsigned b1) {
    asm volatile(
        "mma.sync.aligned.m16n8k8.row.col.f32.tf32.tf32.f32 "
        "{%0,%1,%2,%3}, {%4,%5,%6,%7}, {%8,%9}, {%0,%1,%2,%3};"
        : "+f"(c[0]), "+f"(c[1]), "+f"(c[2]), "+f"(c[3])
        : "r"(a[0]), "r"(a[1]), "r"(a[2]), "r"(a[3]), "r"(b0), "r"(b1));
}

__global__ void k_nop() {}

// ---------------- K1: xg = x @ W_ih^T + b_ih  ([32768,129]@[129,512]) ------
__global__ void k_xg(const float* __restrict__ x,
                     const float* __restrict__ Wih,
                     const float* __restrict__ bih) {
    extern __shared__ float sm[];
    float* xs = sm;            // [64][132]
    float* ws = sm + 64 * 132; // [64][132]
    const int m0 = blockIdx.x * 64;
    const int g0 = blockIdx.y * 64;
    const int tid = threadIdx.x;

    for (int i = tid; i < 64 * 132; i += 256) {
        int r = i / 132, c = i - r * 132;
        xs[i] = (c < 129) ? x[(size_t)(m0 + r) * 129 + c] : 0.f;
    }
    for (int i = tid; i < 64 * 132; i += 256) {
        int r = i / 132, c = i - r * 132;
        ws[i] = (c < 129) ? Wih[(size_t)(g0 + r) * 129 + c] : 0.f;
    }
    __syncthreads();

    const int ty = tid >> 4, tx = tid & 15;
    u64 acc2[4][4] = {};
    const ulonglong2* xs2 = (const ulonglong2*)xs;
    const ulonglong2* ws2 = (const ulonglong2*)ws;

#pragma unroll 3
    for (int k = 0; k < 33; k++) {
        ulonglong2 xv[4], wv[4];
#pragma unroll
        for (int i = 0; i < 4; i++) xv[i] = xs2[(4 * ty + i) * 33 + k];
#pragma unroll
        for (int j = 0; j < 4; j++) wv[j] = ws2[(4 * tx + j) * 33 + k];
#pragma unroll
        for (int i = 0; i < 4; i++)
#pragma unroll
            for (int j = 0; j < 4; j++) {
                fma2(acc2[i][j], xv[i].x, wv[j].x);
                fma2(acc2[i][j], xv[i].y, wv[j].y);
            }
    }

#pragma unroll
    for (int i = 0; i < 4; i++)
#pragma unroll
        for (int j = 0; j < 4; j++) {
            int g = g0 + 4 * tx + j;
            g_xg[(size_t)(m0 + 4 * ty + i) * 512 + g] = hsum2(acc2[i][j]) + bih[g];
        }
}

// ---------------- K2: LSTM, 2 batches per CTA, 512 threads -----------------
// 8 CTAs. Thread t: gate gt=t&3 (i,f,g,o), dim jd=t>>2, row=gt*128+jd.
// Weight row shared across both batches: 64 floats in regs (32 u64), 64
// streamed from smem ([slot][thread], conflict-free LDS.128). Quad-shfl
// combines gates; leaders (gt==0) write h for both batches; 1 barrier/step.
__global__ void __launch_bounds__(512, 1)
k_lstm6(const float* __restrict__ Whh, const float* __restrict__ bhh) {
    extern __shared__ float sm[];
    float4* wsh = (float4*)sm;            // [16][512] float4 (128 KB)
    float*  hb  = sm + 16 * 512 * 4;      // [batch][buf][128] = 4*128 floats

    const int t  = threadIdx.x;
    const int gt = t & 3;                 // 0=i,1=f,2=g,3=o
    const int jd = t >> 2;                // 0..127
    const int row = gt * 128 + jd;
    const int b0 = blockIdx.x * 2, b1 = b0 + 1;

    // weights: floats 0..63 in regs, 64..127 streamed via smem
    u64 w[32];
    {
        const ulonglong2* Wp = (const ulonglong2*)(Whh + (size_t)row * 128);
#pragma unroll
        for (int k = 0; k < 16; k++) { ulonglong2 v = Wp[k]; w[2*k] = v.x; w[2*k+1] = v.y; }
        const float4* Wp4 = (const float4*)(Whh + (size_t)row * 128);
#pragma unroll
        for (int k = 0; k < 16; k++) wsh[k * 512 + t] = Wp4[16 + k];
    }
    const float bg = bhh[row];

    if (t < 128) { hb[t] = 0.f; hb[256 + t] = 0.f; }   // buf0 of both batches
    float c0 = 0.f, c1 = 0.f;

    const float* xg0 = g_xg + (size_t)b0 * 2048 * 512 + row;
    const float* xg1 = g_xg + (size_t)b1 * 2048 * 512 + row;
    float xv0 = xg0[0], xv1 = xg1[0];
    __syncthreads();

    const int lane = t & 31;
    const int qb   = lane & ~3;
    const bool leader = (gt == 0);
    float* gl0 = g_lstm + (size_t)b0 * 2048 * 128 + jd;
    float* gl1 = g_lstm + (size_t)b1 * 2048 * 128 + jd;
    const ulonglong2* wsh2 = (const ulonglong2*)wsh;

    for (int s = 0; s < 2048; s++) {
        float n0 = 0.f, n1 = 0.f;
        if (s + 1 < 2048) {
            n0 = xg0[(size_t)(s + 1) * 512];
            n1 = xg1[(size_t)(s + 1) * 512];
        }
        const int buf = s & 1;
        const ulonglong2* h0 = (const ulonglong2*)(hb + buf * 128);
        const ulonglong2* h1 = (const ulonglong2*)(hb + 256 + buf * 128);

        u64 a00 = 0ull, a01 = 0ull, a10 = 0ull, a11 = 0ull;
        // register weights: h[0..63]
#pragma unroll
        for (int k = 0; k < 16; k++) {
            ulonglong2 p0 = h0[k];
            ulonglong2 p1 = h1[k];
            fma2(a00, w[2*k], p0.x); fma2(a01, w[2*k+1], p0.y);
            fma2(a10, w[2*k], p1.x); fma2(a11, w[2*k+1], p1.y);
        }
        // streamed weights: h[64..127]
#pragma unroll
        for (int k = 0; k < 16; k++) {
            ulonglong2 wv = wsh2[k * 512 + t];
            ulonglong2 p0 = h0[16 + k];
            ulonglong2 p1 = h1[16 + k];
            fma2(a00, wv.x, p0.x); fma2(a01, wv.y, p0.y);
            fma2(a10, wv.x, p1.x); fma2(a11, wv.y, p1.y);
        }
        float pre0 = hsum2(a00) + hsum2(a01) + xv0 + bg;
        float pre1 = hsum2(a10) + hsum2(a11) + xv1 + bg;

        float act0 = (gt == 2) ? tanh_fast(pre0) : sigf(pre0);
        float act1 = (gt == 2) ? tanh_fast(pre1) : sigf(pre1);
        float fa0 = __shfl_sync(0xffffffffu, act0, qb + 1, 32);
        float ga0 = __shfl_sync(0xffffffffu, act0, qb + 2, 32);
        float oa0 = __shfl_sync(0xffffffffu, act0, qb + 3, 32);
        float fa1 = __shfl_sync(0xffffffffu, act1, qb + 1, 32);
        float ga1 = __shfl_sync(0xffffffffu, act1, qb + 2, 32);
        float oa1 = __shfl_sync(0xffffffffu, act1, qb + 3, 32);

        if (leader) {
            const int nb = (s + 1) & 1;
            c0 = fmaf(fa0, c0, act0 * ga0);
            float hv0 = oa0 * tanh_fast(c0);
            gl0[(size_t)s * 128] = hv0;
            hb[nb * 128 + jd] = hv0;
            c1 = fmaf(fa1, c1, act1 * ga1);
            float hv1 = oa1 * tanh_fast(c1);
            gl1[(size_t)s * 128] = hv1;
            hb[256 + nb * 128 + jd] = hv1;
        }
        xv0 = n0; xv1 = n1;
        __syncthreads();
    }
}

// ---------------- K3: flash attention, tf32 mma.sync -----------------------
__global__ void __launch_bounds__(128) k_attn() {
    extern __shared__ float sm[];
    float* qs = sm;                 // [64][132] tf32 bits of q * 1/sqrt(129)
    float* ks = sm + 64 * 132;      // [64][132] tf32 bits of K==V chunk
    float* ps = ks + 64 * 132;      // [64][68]  tf32 probs

    const int b  = blockIdx.y;
    const int r0 = blockIdx.x * 64;
    const float* base = g_lstm + (size_t)b * 2048 * 128;
    const int tid  = threadIdx.x;
    const int warp = tid >> 5, lane = tid & 31;
    const int gid  = lane >> 2, tig = lane & 3;
    const int wr   = warp * 16;
    const float rs = 0.08804509063256238f; // 1/sqrt(129)

    {   // stage q tile: scale + tf32-round
        const float4* qg = (const float4*)(base + (size_t)r0 * 128);
        float4* qs4 = (float4*)qs;
        for (int i = tid; i < 2048; i += 128) {
            int row = i >> 5, c = i & 31;
            float4 v = qg[row * 32 + c];
            v.x = __uint_as_float(tf32of(v.x * rs));
            v.y = __uint_as_float(tf32of(v.y * rs));
            v.z = __uint_as_float(tf32of(v.z * rs));
            v.w = __uint_as_float(tf32of(v.w * rs));
            qs4[row * 33 + c] = v;
        }
    }

    float m0 = -1e30f, m1 = -1e30f, l0 = 0.f, l1 = 0.f;
    float o[16][4];
#pragma unroll
    for (int n = 0; n < 16; n++) { o[n][0]=0.f; o[n][1]=0.f; o[n][2]=0.f; o[n][3]=0.f; }

    const unsigned* qsu = (const unsigned*)qs;
    const unsigned* ksu = (const unsigned*)ks;

    for (int kt = 0; kt < 32; kt++) {
        __syncthreads();
        {   // stage K/V chunk as tf32
            const float4* kg = (const float4*)(base + (size_t)kt * 64 * 128);
            float4* ks4 = (float4*)ks;
            for (int i = tid; i < 2048; i += 128) {
                int row = i >> 5, c = i & 31;
                float4 v = kg[row * 32 + c];
                v.x = __uint_as_float(tf32of(v.x));
                v.y = __uint_as_float(tf32of(v.y));
                v.z = __uint_as_float(tf32of(v.z));
                v.w = __uint_as_float(tf32of(v.w));
                ks4[row * 33 + c] = v;
            }
        }
        __syncthreads();

        // phase 1: S(16x64) = Q @ K^T
        float s[8][4];
#pragma unroll
        for (int n = 0; n < 8; n++) { s[n][0]=0.f; s[n][1]=0.f; s[n][2]=0.f; s[n][3]=0.f; }
#pragma unroll
        for (int kk = 0; kk < 16; kk++) {
            unsigned a[4];
            int cc = kk * 8 + tig;
            a[0] = qsu[(wr + gid)     * 132 + cc];
            a[1] = qsu[(wr + gid + 8) * 132 + cc];
            a[2] = qsu[(wr + gid)     * 132 + cc + 4];
            a[3] = qsu[(wr + gid + 8) * 132 + cc + 4];
#pragma unroll
            for (int n = 0; n < 8; n++) {
                unsigned b0 = ksu[(n * 8 + gid) * 132 + cc];
                unsigned b1 = ksu[(n * 8 + gid) * 132 + cc + 4];
                mma_tf32(s[n], a, b0, b1);
            }
        }

        // online softmax
        float vm0 = -1e30f, vm1 = -1e30f;
#pragma unroll
        for (int n = 0; n < 8; n++) {
            vm0 = fmaxf(vm0, fmaxf(s[n][0], s[n][1]));
            vm1 = fmaxf(vm1, fmaxf(s[n][2], s[n][3]));
        }
        vm0 = fmaxf(vm0, __shfl_xor_sync(0xffffffffu, vm0, 1));
        vm0 = fmaxf(vm0, __shfl_xor_sync(0xffffffffu, vm0, 2));
        vm1 = fmaxf(vm1, __shfl_xor_sync(0xffffffffu, vm1, 1));
        vm1 = fmaxf(vm1, __shfl_xor_sync(0xffffffffu, vm1, 2));
        float nm0 = fmaxf(m0, vm0), nm1 = fmaxf(m1, vm1);

        float sum0 = 0.f, sum1 = 0.f;
#pragma unroll
        for (int n = 0; n < 8; n++) {
            float p0 = __expf(s[n][0] - nm0);
            float p1 = __expf(s[n][1] - nm0);
            float p2 = __expf(s[n][2] - nm1);
            float p3 = __expf(s[n][3] - nm1);
            sum0 += p0 + p1; sum1 += p2 + p3;
            float* pp = ps + (wr + gid) * 68 + n * 8 + 2 * tig;
            pp[0] = __uint_as_float(tf32of(p0));
            pp[1] = __uint_as_float(tf32of(p1));
            float* pq = ps + (wr + gid + 8) * 68 + n * 8 + 2 * tig;
            pq[0] = __uint_as_float(tf32of(p2));
            pq[1] = __uint_as_float(tf32of(p3));
        }
        sum0 += __shfl_xor_sync(0xffffffffu, sum0, 1);
        sum0 += __shfl_xor_sync(0xffffffffu, sum0, 2);
        sum1 += __shfl_xor_sync(0xffffffffu, sum1, 1);
        sum1 += __shfl_xor_sync(0xffffffffu, sum1, 2);
        float alpha0 = __expf(m0 - nm0), alpha1 = __expf(m1 - nm1);
        l0 = l0 * alpha0 + sum0; m0 = nm0;
        l1 = l1 * alpha1 + sum1; m1 = nm1;
        __syncwarp();

        // phase 2: O(16x128) += P @ V
#pragma unroll
        for (int n = 0; n < 16; n++) {
            o[n][0] *= alpha0; o[n][1] *= alpha0;
            o[n][2] *= alpha1; o[n][3] *= alpha1;
        }
        const unsigned* psu = (const unsigned*)ps;
#pragma unroll
        for (int kk = 0; kk < 8; kk++) {
            unsigned pa[4];
            pa[0] = psu[(wr + gid)     * 68 + kk * 8 + tig];
            pa[1] = psu[(wr + gid + 8) * 68 + kk * 8 + tig];
            pa[2] = psu[(wr + gid)     * 68 + kk * 8 + tig + 4];
            pa[3] = psu[(wr + gid + 8) * 68 + kk * 8 + tig + 4];
#pragma unroll
            for (int n = 0; n < 16; n++) {
                unsigned b0 = ksu[(kk * 8 + tig)     * 132 + n * 8 + gid];
                unsigned b1 = ksu[(kk * 8 + tig + 4) * 132 + n * 8 + gid];
                mma_tf32(o[n], pa, b0, b1);
            }
        }
    }

    // epilogue
    float inv0 = 1.f / l0, inv1 = 1.f / l1;
    int row0 = r0 + wr + gid, row1 = row0 + 8;
    float* d0 = g_ctx + ((size_t)b * 2048 + row0) * 128;
    float* d1 = g_ctx + ((size_t)b * 2048 + row1) * 128;
#pragma unroll
    for (int n = 0; n < 16; n++) {
        int cc = n * 8 + 2 * tig;
        *(float2*)(d0 + cc) = make_float2(o[n][0] * inv0, o[n][1] * inv0);
        *(float2*)(d1 + cc) = make_float2(o[n][2] * inv1, o[n][3] * inv1);
    }
}

// ---------------- K4: concat(context, RBF kernel feature), pad to 132 ------
__global__ void k_feat(const float* __restrict__ x, const float* __restrict__ pr) {
    const int tid = threadIdx.x;
    const int warp = tid >> 5, lane = tid & 31;
    const size_t mrow = (size_t)blockIdx.x * 8 + warp;

    const float4* c4 = (const float4*)(g_ctx + mrow * 128);
    float4* o4 = (float4*)(g_ha + mrow * 132);
    o4[lane] = c4[lane];

    const float* xr = x  + mrow * 129;
    const float* pp = pr + mrow * 129;
    float ss = 0.f;
    for (int j2 = lane; j2 < 129; j2 += 32) {
        float d = xr[j2] - pp[j2];
        ss += d * d;
    }
#pragma unroll
    for (int dd = 16; dd; dd >>= 1) ss += __shfl_xor_sync(0xffffffffu, ss, dd);
    if (lane == 0)      g_ha[mrow * 132 + 128] = __expf(-ss);
    else if (lane < 4)  g_ha[mrow * 132 + 128 + lane] = 0.f;
}

// ---------------- K5: MLP layer via tf32 mma: h=relu(h@Wc[l]^T+bc[l]) ------
// 128 threads (4 warps), 64 rows/block. W (tf32) [136 outcols][136 j] in smem;
// in tile (tf32) [64][136]. Same fragment mapping as k_attn phase 1.
__global__ void __launch_bounds__(128) k_mlp_t(const float* __restrict__ Wc,
                                               const float* __restrict__ bc, int l) {
    extern __shared__ float sm[];
    float* Wsh  = sm;               // [136][136]
    float* insh = sm + 136 * 136;   // [64][136]
    const float* in  = (l & 1) ? g_hb : g_ha;
    float*       out = (l & 1) ? g_ha : g_hb;

    const int m0 = blockIdx.x * 64;
    const int tid = threadIdx.x;
    const int warp = tid >> 5, lane = tid & 31;
    const int gid  = lane >> 2, tig = lane & 3;
    const int wr   = warp * 16;
    const float* W  = Wc + (size_t)l * 129 * 129;
    const float* bb = bc + (size_t)l * 129;

    for (int i = tid; i < 136 * 136; i += 128) {
        int r = i / 136, c = i - r * 136;
        float v = (r < 129 && c < 129) ? W[r * 129 + c] : 0.f;
        Wsh[i] = __uint_as_float(tf32of(v));
    }
    for (int i = tid; i < 64 * 136; i += 128) {
        int r = i / 136, c = i - r * 136;
        float v = (c < 132) ? in[(size_t)(m0 + r) * 132 + c] : 0.f;
        insh[i] = __uint_as_float(tf32of(v));
    }
    __syncthreads();

    const unsigned* inu = (const unsigned*)insh;
    const unsigned* Wu  = (const unsigned*)Wsh;

    float s[17][4];
#pragma unroll
    for (int n = 0; n < 17; n++) { s[n][0]=0.f; s[n][1]=0.f; s[n][2]=0.f; s[n][3]=0.f; }

#pragma unroll
    for (int kk = 0; kk < 17; kk++) {
        unsigned a[4];
        int cc = kk * 8 + tig;
        a[0] = inu[(wr + gid)     * 136 + cc];
        a[1] = inu[(wr + gid + 8) * 136 + cc];
        a[2] = inu[(wr + gid)     * 136 + cc + 4];
        a[3] = inu[(wr + gid + 8) * 136 + cc + 4];
#pragma unroll
        for (int n = 0; n < 17; n++) {
            unsigned b0 = Wu[(n * 8 + gid) * 136 + cc];
            unsigned b1 = Wu[(n * 8 + gid) * 136 + cc + 4];
            mma_tf32(s[n], a, b0, b1);
        }
    }

    // epilogue: bias + relu, cols 0..131 stored (cols 129..131 are 0)
    int r0 = m0 + wr + gid, r1 = r0 + 8;
#pragma unroll
    for (int n = 0; n < 17; n++) {
        int col = n * 8 + 2 * tig;
        if (col < 132) {
            float bv0 = (col     < 129) ? bb[col]     : 0.f;
            float bv1 = (col + 1 < 129) ? bb[col + 1] : 0.f;
            out[(size_t)r0 * 132 + col]     = fmaxf(s[n][0] + bv0, 0.f);
            out[(size_t)r0 * 132 + col + 1] = fmaxf(s[n][1] + bv1, 0.f);
            out[(size_t)r1 * 132 + col]     = fmaxf(s[n][2] + bv0, 0.f);
            out[(size_t)r1 * 132 + col + 1] = fmaxf(s[n][3] + bv1, 0.f);
        }
    }
}

// ---------------- K6: head + log_softmax -----------------------------------
__global__ void k_head(const float* __restrict__ Wh, const float* __restrict__ bh,
                       float* __restrict__ out) {
    const int tid = threadIdx.x;
    const int warp = tid >> 5, lane = tid & 31;
    const size_t mrow = (size_t)blockIdx.x * 8 + warp;
    const float* hr = g_ha + mrow * 132;

    float s0 = 0.f, s1 = 0.f;
    for (int j2 = lane; j2 < 129; j2 += 32) {
        float hv = hr[j2];
        s0 += hv * Wh[j2];
        s1 += hv * Wh[129 + j2];
    }
#pragma unroll
    for (int dd = 16; dd; dd >>= 1) {
        s0 += __shfl_xor_sync(0xffffffffu, s0, dd);
        s1 += __shfl_xor_sync(0xffffffffu, s1, dd);
    }
    if (lane == 0) {
        s0 += bh[0]; s1 += bh[1];
        float mx = fmaxf(s0, s1);
        float lse = mx + logf(__expf(s0 - mx) + __expf(s1 - mx));
        out[2 * mrow]     = s0 - lse;
        out[2 * mrow + 1] = s1 - lse;
    }
}

// ---------------- launch ---------------------------------------------------
extern "C" void kernel_launch(void* const* d_in, const int* in_sizes, int n_in,
                              void* d_out, int out_size) {
    const float* x     = (const float*)d_in[0];
    const float* proto = (const float*)d_in[1];
    const float* Wih   = (const float*)d_in[2];
    const float* Whh   = (const float*)d_in[3];
    const float* bih   = (const float*)d_in[4];
    const float* bhh   = (const float*)d_in[5];
    const float* Wc    = (const float*)d_in[6];
    const float* bc    = (const float*)d_in[7];
    const float* Wh    = (const float*)d_in[8];
    const float* bh    = (const float*)d_in[9];
    float* out = (float*)d_out;

    const int smem_xg   = 2 * 64 * 132 * 4;                 // 67584
    const int smem_lstm = 16 * 512 * 16 + 4 * 128 * 4;      // 133120
    const int smem_attn = (2 * 64 * 132 + 64 * 68) * 4;     // 84992
    const int smem_mlp  = (136 * 136 + 64 * 136) * 4;       // 108800

    cudaFuncSetAttribute(k_xg,    cudaFuncAttributeMaxDynamicSharedMemorySize, smem_xg);
    cudaFuncSetAttribute(k_lstm6, cudaFuncAttributeMaxDynamicSharedMemorySize, smem_lstm);
    cudaFuncSetAttribute(k_attn,  cudaFuncAttributeMaxDynamicSharedMemorySize, smem_attn);
    cudaFuncSetAttribute(k_mlp_t, cudaFuncAttributeMaxDynamicSharedMemorySize, smem_mlp);

    k_xg  <<<dim3(512, 8), 256, smem_xg>>>(x, Wih, bih);
    k_nop <<<1, 32>>>();          // shift ncu slot:
    k_nop <<<1, 32>>>();          // ... so launch #4 is k_lstm6
    k_lstm6<<<8, 512, smem_lstm>>>(Whh, bhh);   // 2 batches per CTA
    k_attn<<<dim3(32, 16), 128, smem_attn>>>();
    k_feat<<<4096,         256>>>(x, proto);
    for (int l = 0; l < 4; l++)
        k_mlp_t<<<512, 128, smem_mlp>>>(Wc, bc, l);
    k_head<<<4096, 256>>>(Wh, bh, out);
}

// round 11
// speedup vs baseline: 1.5585x; 1.5585x over previous
#include <cuda_runtime.h>
#include <math.h>
#include <stdint.h>

typedef unsigned long long u64;

// ---------------- scratch (device globals; no allocation allowed) ----------
__device__ float g_xg  [16u*2048u*512u];   // precomputed input gates [B,S,4H]
__device__ float g_lstm[16u*2048u*128u];   // lstm hidden states [B,S,H]
__device__ float g_ctx [16u*2048u*128u];   // attention context [B,S,H]
__device__ float g_ha  [32768u*132u];      // MLP ping buffer (stride 132)
__device__ float g_hb  [32768u*132u];      // MLP pong buffer

__device__ __forceinline__ float tanha(float x) {
    float r; asm("tanh.approx.f32 %0, %1;" : "=f"(r) : "f"(x)); return r;
}
__device__ __forceinline__ float sigt(float x) {       // sigmoid via MUFU.TANH
    return fmaf(0.5f, tanha(0.5f * x), 0.5f);
}

// packed f32x2 helpers ------------------------------------------------------
__device__ __forceinline__ void fma2(u64& c, u64 a, u64 b) {
    asm("fma.rn.f32x2 %0, %1, %2, %0;" : "+l"(c) : "l"(a), "l"(b));
}
__device__ __forceinline__ float2 upk(u64 v) {
    unsigned lo, hi;
    asm("mov.b64 {%0, %1}, %2;" : "=r"(lo), "=r"(hi) : "l"(v));
    return make_float2(__uint_as_float(lo), __uint_as_float(hi));
}
__device__ __forceinline__ float hsum2(u64 v) { float2 f = upk(v); return f.x + f.y; }

// tf32 helpers ---------------------------------------------------------------
__device__ __forceinline__ unsigned tf32of(float f) {
    unsigned u; asm("cvt.rna.tf32.f32 %0, %1;" : "=r"(u) : "f"(f)); return u;
}
__device__ __forceinline__ void mma_tf32(float* c, const unsigned* a,
                                         unsigned b0, unsigned b1) {
    asm volatile(
        "mma.sync.aligned.m16n8k8.row.col.f32.tf32.tf32.f32 "
        "{%0,%1,%2,%3}, {%4,%5,%6,%7}, {%8,%9}, {%0,%1,%2,%3};"
        : "+f"(c[0]), "+f"(c[1]), "+f"(c[2]), "+f"(c[3])
        : "r"(a[0]), "r"(a[1]), "r"(a[2]), "r"(a[3]), "r"(b0), "r"(b1));
}

__global__ void k_nop() {}

// ---------------- K1: xg = x @ W_ih^T + b_ih  ([32768,129]@[129,512]) ------
__global__ void k_xg(const float* __restrict__ x,
                     const float* __restrict__ Wih,
                     const float* __restrict__ bih) {
    extern __shared__ float sm[];
    float* xs = sm;            // [64][132]
    float* ws = sm + 64 * 132; // [64][132]
    const int m0 = blockIdx.x * 64;
    const int g0 = blockIdx.y * 64;
    const int tid = threadIdx.x;

    for (int i = tid; i < 64 * 132; i += 256) {
        int r = i / 132, c = i - r * 132;
        xs[i] = (c < 129) ? x[(size_t)(m0 + r) * 129 + c] : 0.f;
    }
    for (int i = tid; i < 64 * 132; i += 256) {
        int r = i / 132, c = i - r * 132;
        ws[i] = (c < 129) ? Wih[(size_t)(g0 + r) * 129 + c] : 0.f;
    }
    __syncthreads();

    const int ty = tid >> 4, tx = tid & 15;
    u64 acc2[4][4] = {};
    const ulonglong2* xs2 = (const ulonglong2*)xs;
    const ulonglong2* ws2 = (const ulonglong2*)ws;

#pragma unroll 3
    for (int k = 0; k < 33; k++) {
        ulonglong2 xv[4], wv[4];
#pragma unroll
        for (int i = 0; i < 4; i++) xv[i] = xs2[(4 * ty + i) * 33 + k];
#pragma unroll
        for (int j = 0; j < 4; j++) wv[j] = ws2[(4 * tx + j) * 33 + k];
#pragma unroll
        for (int i = 0; i < 4; i++)
#pragma unroll
            for (int j = 0; j < 4; j++) {
                fma2(acc2[i][j], xv[i].x, wv[j].x);
                fma2(acc2[i][j], xv[i].y, wv[j].y);
            }
    }

#pragma unroll
    for (int i = 0; i < 4; i++)
#pragma unroll
        for (int j = 0; j < 4; j++) {
            int g = g0 + 4 * tx + j;
            g_xg[(size_t)(m0 + 4 * ty + i) * 512 + g] = hsum2(acc2[i][j]) + bih[g];
        }
}

// ---------------- K2: LSTM recurrence (16 blocks, 256 threads) — PROVEN ----
// thread t: j = t>>1; even -> gates (i: j, g: 256+j); odd -> (f: 128+j, o: 384+j)
// 80 weights/gate in registers, 48/gate streamed from smem, h double-buffered.
__global__ void __launch_bounds__(256, 1)
k_lstm(const float* __restrict__ Whh, const float* __restrict__ bhh) {
    extern __shared__ float sm[];
    float4* wsh = (float4*)sm;            // 24 slots * 256 threads of float4
    float*  hb  = sm + 4 * 24 * 256;      // [2][128] double-buffered h

    const int b = blockIdx.x;
    const int t = threadIdx.x;
    const int j = t >> 1;
    const bool odd = (t & 1);
    const int gA = odd ? (128 + j) : j;
    const int gB = gA + 256;

    const ulonglong2* WA = (const ulonglong2*)(Whh + (size_t)gA * 128);
    const ulonglong2* WB = (const ulonglong2*)(Whh + (size_t)gB * 128);
    ulonglong2 wA[20], wB[20];
#pragma unroll
    for (int k = 0; k < 20; k++) { wA[k] = WA[k]; wB[k] = WB[k]; }
    {
        const float4* WA4 = (const float4*)WA;
        const float4* WB4 = (const float4*)WB;
#pragma unroll
        for (int k = 0; k < 12; k++) {
            wsh[k * 256 + t]        = WA4[20 + k];
            wsh[(12 + k) * 256 + t] = WB4[20 + k];
        }
    }
    const float bA = bhh[gA], bB = bhh[gB];

    if (t < 128) hb[t] = 0.f;
    float c = 0.f;

    const float* xgp = g_xg + (size_t)b * 2048 * 512;
    float xgA = xgp[gA], xgB = xgp[gB];
    __syncthreads();

    const ulonglong2* wsh2 = (const ulonglong2*)wsh;

    for (int s = 0; s < 2048; s++) {
        float nA = 0.f, nB = 0.f;
        if (s + 1 < 2048) {
            nA = xgp[(size_t)(s + 1) * 512 + gA];
            nB = xgp[(size_t)(s + 1) * 512 + gB];
        }

        const ulonglong2* h2 = (const ulonglong2*)(hb + (s & 1) * 128);
        u64 a0 = 0ull, a1 = 0ull, d0 = 0ull, d1 = 0ull;
#pragma unroll
        for (int k = 0; k < 20; k++) {
            ulonglong2 hv = h2[k];
            fma2(a0, wA[k].x, hv.x); fma2(a1, wA[k].y, hv.y);
            fma2(d0, wB[k].x, hv.x); fma2(d1, wB[k].y, hv.y);
        }
#pragma unroll
        for (int k = 0; k < 12; k++) {
            ulonglong2 hv = h2[20 + k];
            ulonglong2 wa = wsh2[k * 256 + t];
            ulonglong2 wb = wsh2[(12 + k) * 256 + t];
            fma2(a0, wa.x, hv.x); fma2(a1, wa.y, hv.y);
            fma2(d0, wb.x, hv.x); fma2(d1, wb.y, hv.y);
        }
        float a = hsum2(a0) + hsum2(a1);
        float d = hsum2(d0) + hsum2(d1);

        float pre0 = a + xgA + bA;
        float pre1 = d + xgB + bB;
        float q0 = __shfl_xor_sync(0xffffffffu, pre0, 1);
        float q1 = __shfl_xor_sync(0xffffffffu, pre1, 1);
        float ip, fp, gp, op;
        if (!odd) { ip = pre0; gp = pre1; fp = q0;   op = q1;   }
        else      { ip = q0;   gp = q1;   fp = pre0; op = pre1; }

        // MUFU.TANH-based activations (1 op each)
        c = sigt(fp) * c + sigt(ip) * tanha(gp);
        float h = sigt(op) * tanha(c);

        float* hn = hb + ((s + 1) & 1) * 128;
        if (!odd) {
            hn[j] = h;
            g_lstm[((size_t)b * 2048 + s) * 128 + j] = h;
        }
        xgA = nA; xgB = nB;
        __syncthreads();
    }
}

// ---------------- K3: flash attention, tf32 mma, 256 threads ---------------
// 8 warps = 2 q-tiles of 64 rows sharing each K/V chunk (halves staging/row,
// doubles warps/SMSP for latency hiding). Per-warp logic identical to the
// proven 128-thread version.
__global__ void __launch_bounds__(256) k_attn() {
    extern __shared__ float sm[];
    float* qs = sm;                  // [128][132] tf32(q * 1/sqrt(129))
    float* ks = sm + 128 * 132;      // [64][132]  tf32 K==V chunk
    float* ps = ks + 64 * 132;       // [128][68]  tf32 probs

    const int b   = blockIdx.y;
    const int rq0 = blockIdx.x * 128;
    const float* base = g_lstm + (size_t)b * 2048 * 128;
    const int tid  = threadIdx.x;
    const int warp = tid >> 5, lane = tid & 31;
    const int tile = warp >> 2;          // 0 or 1
    const int w4   = warp & 3;
    const int gid  = lane >> 2, tig = lane & 3;
    const int wr   = w4 * 16;
    const float rs = 0.08804509063256238f; // 1/sqrt(129)

    {   // stage both q tiles (128 rows): scale + tf32-round
        const float4* qg = (const float4*)(base + (size_t)rq0 * 128);
        float4* qs4 = (float4*)qs;
        for (int i = tid; i < 4096; i += 256) {
            int row = i >> 5, c = i & 31;
            float4 v = qg[row * 32 + c];
            v.x = __uint_as_float(tf32of(v.x * rs));
            v.y = __uint_as_float(tf32of(v.y * rs));
            v.z = __uint_as_float(tf32of(v.z * rs));
            v.w = __uint_as_float(tf32of(v.w * rs));
            qs4[row * 33 + c] = v;
        }
    }

    float m0 = -1e30f, m1 = -1e30f, l0 = 0.f, l1 = 0.f;
    float o[16][4];
#pragma unroll
    for (int n = 0; n < 16; n++) { o[n][0]=0.f; o[n][1]=0.f; o[n][2]=0.f; o[n][3]=0.f; }

    const unsigned* qsu = (const unsigned*)qs + tile * 64 * 132;
    const unsigned* ksu = (const unsigned*)ks;
    float* psT = ps + tile * 64 * 68;

    for (int kt = 0; kt < 32; kt++) {
        __syncthreads();   // prior phase-2 reads of ks done (also covers q stage)
        {   // stage K/V chunk as tf32
            const float4* kg = (const float4*)(base + (size_t)kt * 64 * 128);
            float4* ks4 = (float4*)ks;
            for (int i = tid; i < 2048; i += 256) {
                int row = i >> 5, c = i & 31;
                float4 v = kg[row * 32 + c];
                v.x = __uint_as_float(tf32of(v.x));
                v.y = __uint_as_float(tf32of(v.y));
                v.z = __uint_as_float(tf32of(v.z));
                v.w = __uint_as_float(tf32of(v.w));
                ks4[row * 33 + c] = v;
            }
        }
        __syncthreads();

        // phase 1: S(16x64) = Q @ K^T
        float s[8][4];
#pragma unroll
        for (int n = 0; n < 8; n++) { s[n][0]=0.f; s[n][1]=0.f; s[n][2]=0.f; s[n][3]=0.f; }
#pragma unroll
        for (int kk = 0; kk < 16; kk++) {
            unsigned a[4];
            int cc = kk * 8 + tig;
            a[0] = qsu[(wr + gid)     * 132 + cc];
            a[1] = qsu[(wr + gid + 8) * 132 + cc];
            a[2] = qsu[(wr + gid)     * 132 + cc + 4];
            a[3] = qsu[(wr + gid + 8) * 132 + cc + 4];
#pragma unroll
            for (int n = 0; n < 8; n++) {
                unsigned b0 = ksu[(n * 8 + gid) * 132 + cc];
                unsigned b1 = ksu[(n * 8 + gid) * 132 + cc + 4];
                mma_tf32(s[n], a, b0, b1);
            }
        }

        // online softmax (rows wr+gid and wr+gid+8 of this tile)
        float vm0 = -1e30f, vm1 = -1e30f;
#pragma unroll
        for (int n = 0; n < 8; n++) {
            vm0 = fmaxf(vm0, fmaxf(s[n][0], s[n][1]));
            vm1 = fmaxf(vm1, fmaxf(s[n][2], s[n][3]));
        }
        vm0 = fmaxf(vm0, __shfl_xor_sync(0xffffffffu, vm0, 1));
        vm0 = fmaxf(vm0, __shfl_xor_sync(0xffffffffu, vm0, 2));
        vm1 = fmaxf(vm1, __shfl_xor_sync(0xffffffffu, vm1, 1));
        vm1 = fmaxf(vm1, __shfl_xor_sync(0xffffffffu, vm1, 2));
        float nm0 = fmaxf(m0, vm0), nm1 = fmaxf(m1, vm1);

        float sum0 = 0.f, sum1 = 0.f;
#pragma unroll
        for (int n = 0; n < 8; n++) {
            float p0 = __expf(s[n][0] - nm0);
            float p1 = __expf(s[n][1] - nm0);
            float p2 = __expf(s[n][2] - nm1);
            float p3 = __expf(s[n][3] - nm1);
            sum0 += p0 + p1; sum1 += p2 + p3;
            float* pp = psT + (wr + gid) * 68 + n * 8 + 2 * tig;
            pp[0] = __uint_as_float(tf32of(p0));
            pp[1] = __uint_as_float(tf32of(p1));
            float* pq = psT + (wr + gid + 8) * 68 + n * 8 + 2 * tig;
            pq[0] = __uint_as_float(tf32of(p2));
            pq[1] = __uint_as_float(tf32of(p3));
        }
        sum0 += __shfl_xor_sync(0xffffffffu, sum0, 1);
        sum0 += __shfl_xor_sync(0xffffffffu, sum0, 2);
        sum1 += __shfl_xor_sync(0xffffffffu, sum1, 1);
        sum1 += __shfl_xor_sync(0xffffffffu, sum1, 2);
        float alpha0 = __expf(m0 - nm0), alpha1 = __expf(m1 - nm1);
        l0 = l0 * alpha0 + sum0; m0 = nm0;
        l1 = l1 * alpha1 + sum1; m1 = nm1;
        __syncwarp();   // ps written/read within the same warp only

        // phase 2: O(16x128) += P @ V
#pragma unroll
        for (int n = 0; n < 16; n++) {
            o[n][0] *= alpha0; o[n][1] *= alpha0;
            o[n][2] *= alpha1; o[n][3] *= alpha1;
        }
        const unsigned* psu = (const unsigned*)psT;
#pragma unroll
        for (int kk = 0; kk < 8; kk++) {
            unsigned pa[4];
            pa[0] = psu[(wr + gid)     * 68 + kk * 8 + tig];
            pa[1] = psu[(wr + gid + 8) * 68 + kk * 8 + tig];
            pa[2] = psu[(wr + gid)     * 68 + kk * 8 + tig + 4];
            pa[3] = psu[(wr + gid + 8) * 68 + kk * 8 + tig + 4];
#pragma unroll
            for (int n = 0; n < 16; n++) {
                unsigned b0 = ksu[(kk * 8 + tig)     * 132 + n * 8 + gid];
                unsigned b1 = ksu[(kk * 8 + tig + 4) * 132 + n * 8 + gid];
                mma_tf32(o[n], pa, b0, b1);
            }
        }
    }

    // epilogue
    float inv0 = 1.f / l0, inv1 = 1.f / l1;
    int row0 = rq0 + tile * 64 + wr + gid, row1 = row0 + 8;
    float* d0 = g_ctx + ((size_t)b * 2048 + row0) * 128;
    float* d1 = g_ctx + ((size_t)b * 2048 + row1) * 128;
#pragma unroll
    for (int n = 0; n < 16; n++) {
        int cc = n * 8 + 2 * tig;
        *(float2*)(d0 + cc) = make_float2(o[n][0] * inv0, o[n][1] * inv0);
        *(float2*)(d1 + cc) = make_float2(o[n][2] * inv1, o[n][3] * inv1);
    }
}

// ---------------- K4: concat(context, RBF kernel feature), pad to 132 ------
__global__ void k_feat(const float* __restrict__ x, const float* __restrict__ pr) {
    const int tid = threadIdx.x;
    const int warp = tid >> 5, lane = tid & 31;
    const size_t mrow = (size_t)blockIdx.x * 8 + warp;

    const float4* c4 = (const float4*)(g_ctx + mrow * 128);
    float4* o4 = (float4*)(g_ha + mrow * 132);
    o4[lane] = c4[lane];

    const float* xr = x  + mrow * 129;
    const float* pp = pr + mrow * 129;
    float ss = 0.f;
    for (int j2 = lane; j2 < 129; j2 += 32) {
        float d = xr[j2] - pp[j2];
        ss += d * d;
    }
#pragma unroll
    for (int dd = 16; dd; dd >>= 1) ss += __shfl_xor_sync(0xffffffffu, ss, dd);
    if (lane == 0)      g_ha[mrow * 132 + 128] = __expf(-ss);
    else if (lane < 4)  g_ha[mrow * 132 + 128 + lane] = 0.f;
}

// ---------------- K5: one MLP layer h = relu(h @ Wc[l]^T + bc[l]) — PROVEN -
__global__ void k_mlp(const float* __restrict__ Wc, const float* __restrict__ bc, int l) {
    extern __shared__ float sm[];
    float* Wsh  = sm;              // [132][134]
    float* insh = sm + 132 * 134;  // [64][132]
    const float* in  = (l & 1) ? g_hb : g_ha;
    float*       out = (l & 1) ? g_ha : g_hb;

    const int m0 = blockIdx.x * 64;
    const int tid = threadIdx.x;
    const float* W  = Wc + (size_t)l * 129 * 129;
    const float* bb = bc + (size_t)l * 129;

    for (int i = tid; i < 132 * 134; i += 256) {
        int r = i / 134, c = i - r * 134;
        Wsh[i] = (r < 129 && c < 129) ? W[r * 129 + c] : 0.f;
    }
    for (int i = tid; i < 64 * 132; i += 256)
        insh[i] = in[(size_t)m0 * 132 + i];
    __syncthreads();

    const int warp = tid >> 5, lane = tid & 31;
    const int rb = warp * 8;
    const u64* W2 = (const u64*)Wsh;   // row stride 67 pairs

#pragma unroll
    for (int q = 0; q < 2; q++) {
        u64 acc2[4][5] = {};
        const int r0 = rb + 4 * q;
        const u64* h0p = (const u64*)(insh + (r0 + 0) * 132);
        const u64* h1p = (const u64*)(insh + (r0 + 1) * 132);
        const u64* h2p = (const u64*)(insh + (r0 + 2) * 132);
        const u64* h3p = (const u64*)(insh + (r0 + 3) * 132);
#pragma unroll 2
        for (int jp = 0; jp < 66; jp++) {
            u64 h0 = h0p[jp], h1 = h1p[jp], h2 = h2p[jp], h3 = h3p[jp];
#pragma unroll
            for (int cg = 0; cg < 5; cg++) {
                int cc = lane + 32 * cg;
                if (cc < 132) {
                    u64 w = W2[cc * 67 + jp];
                    fma2(acc2[0][cg], h0, w); fma2(acc2[1][cg], h1, w);
                    fma2(acc2[2][cg], h2, w); fma2(acc2[3][cg], h3, w);
                }
            }
        }
#pragma unroll
        for (int cg = 0; cg < 5; cg++) {
            int cc = lane + 32 * cg;
            if (cc < 132) {
                float bv = (cc < 129) ? bb[cc] : 0.f;
#pragma unroll
                for (int i = 0; i < 4; i++)
                    out[(size_t)(m0 + rb + 4 * q + i) * 132 + cc] =
                        fmaxf(hsum2(acc2[i][cg]) + bv, 0.f);
            }
        }
    }
}

// ---------------- K6: head + log_softmax -----------------------------------
__global__ void k_head(const float* __restrict__ Wh, const float* __restrict__ bh,
                       float* __restrict__ out) {
    const int tid = threadIdx.x;
    const int warp = tid >> 5, lane = tid & 31;
    const size_t mrow = (size_t)blockIdx.x * 8 + warp;
    const float* hr = g_ha + mrow * 132;

    float s0 = 0.f, s1 = 0.f;
    for (int j2 = lane; j2 < 129; j2 += 32) {
        float hv = hr[j2];
        s0 += hv * Wh[j2];
        s1 += hv * Wh[129 + j2];
    }
#pragma unroll
    for (int dd = 16; dd; dd >>= 1) {
        s0 += __shfl_xor_sync(0xffffffffu, s0, dd);
        s1 += __shfl_xor_sync(0xffffffffu, s1, dd);
    }
    if (lane == 0) {
        s0 += bh[0]; s1 += bh[1];
        float mx = fmaxf(s0, s1);
        float lse = mx + logf(__expf(s0 - mx) + __expf(s1 - mx));
        out[2 * mrow]     = s0 - lse;
        out[2 * mrow + 1] = s1 - lse;
    }
}

// ---------------- launch ---------------------------------------------------
extern "C" void kernel_launch(void* const* d_in, const int* in_sizes, int n_in,
                              void* d_out, int out_size) {
    const float* x     = (const float*)d_in[0];
    const float* proto = (const float*)d_in[1];
    const float* Wih   = (const float*)d_in[2];
    const float* Whh   = (const float*)d_in[3];
    const float* bih   = (const float*)d_in[4];
    const float* bhh   = (const float*)d_in[5];
    const float* Wc    = (const float*)d_in[6];
    const float* bc    = (const float*)d_in[7];
    const float* Wh    = (const float*)d_in[8];
    const float* bh    = (const float*)d_in[9];
    float* out = (float*)d_out;

    const int smem_xg   = 2 * 64 * 132 * 4;                     // 67584
    const int smem_lstm = (24 * 256 * 4 + 2 * 128) * 4;         // 99328
    const int smem_attn = (128 * 132 + 64 * 132 + 128 * 68) * 4; // 136192
    const int smem_mlp  = (132 * 134 + 64 * 132) * 4;           // 104544

    cudaFuncSetAttribute(k_xg,   cudaFuncAttributeMaxDynamicSharedMemorySize, smem_xg);
    cudaFuncSetAttribute(k_lstm, cudaFuncAttributeMaxDynamicSharedMemorySize, smem_lstm);
    cudaFuncSetAttribute(k_attn, cudaFuncAttributeMaxDynamicSharedMemorySize, smem_attn);
    cudaFuncSetAttribute(k_mlp,  cudaFuncAttributeMaxDynamicSharedMemorySize, smem_mlp);

    k_xg  <<<dim3(512, 8), 256, smem_xg>>>(x, Wih, bih);
    k_lstm<<<16,           256, smem_lstm>>>(Whh, bhh);
    k_nop <<<1, 32>>>();          // shift ncu slot: launch #4 = k_attn
    k_attn<<<dim3(16, 16), 256, smem_attn>>>();
    k_feat<<<4096,         256>>>(x, proto);
    for (int l = 0; l < 4; l++)
        k_mlp<<<512, 256, smem_mlp>>>(Wc, bc, l);
    k_head<<<4096, 256>>>(Wh, bh, out);
}

// round 12
// speedup vs baseline: 1.8569x; 1.1915x over previous
#include <cuda_runtime.h>
#include <cuda_fp16.h>
#include <math.h>
#include <stdint.h>

typedef unsigned long long u64;

// ---------------- scratch (device globals; no allocation allowed) ----------
__device__ float g_xg  [16u*2048u*512u];   // precomputed input gates [B,S,4H]
__device__ float g_lstm[16u*2048u*128u];   // lstm hidden states [B,S,H]
__device__ float g_ctx [16u*2048u*128u];   // attention context [B,S,H]
__device__ float g_ha  [32768u*132u];      // MLP ping buffer (stride 132)
__device__ float g_hb  [32768u*132u];      // MLP pong buffer

__device__ __forceinline__ float sigf(float x) {
    return __fdividef(1.f, 1.f + __expf(-x));
}
__device__ __forceinline__ float tanh_fast(float x) {
    return fmaf(2.f, sigf(2.f * x), -1.f);
}

// packed f32x2 helpers ------------------------------------------------------
__device__ __forceinline__ void fma2(u64& c, u64 a, u64 b) {
    asm("fma.rn.f32x2 %0, %1, %2, %0;" : "+l"(c) : "l"(a), "l"(b));
}
__device__ __forceinline__ u64 pk(float x, float y) {
    u64 r;
    asm("mov.b64 %0, {%1, %2};" : "=l"(r)
        : "r"(__float_as_uint(x)), "r"(__float_as_uint(y)));
    return r;
}
__device__ __forceinline__ float2 upk(u64 v) {
    unsigned lo, hi;
    asm("mov.b64 {%0, %1}, %2;" : "=r"(lo), "=r"(hi) : "l"(v));
    return make_float2(__uint_as_float(lo), __uint_as_float(hi));
}
__device__ __forceinline__ float hsum2(u64 v) { float2 f = upk(v); return f.x + f.y; }
__device__ __forceinline__ u64 h2f2(unsigned h2bits) {   // half2 -> packed f32x2
    __half2 h = *(__half2*)&h2bits;
    float2 f = __half22float2(h);
    return pk(f.x, f.y);
}
__device__ __forceinline__ unsigned f2h2(float x, float y) {
    __half2 h = __floats2half2_rn(x, y);
    return *(unsigned*)&h;
}

// tf32 helpers ---------------------------------------------------------------
__device__ __forceinline__ unsigned tf32of(float f) {
    unsigned u; asm("cvt.rna.tf32.f32 %0, %1;" : "=r"(u) : "f"(f)); return u;
}
__device__ __forceinline__ void mma_tf32(float* c, const unsigned* a,
                                         unsigned b0, unsigned b1) {
    asm volatile(
        "mma.sync.aligned.m16n8k8.row.col.f32.tf32.tf32.f32 "
        "{%0,%1,%2,%3}, {%4,%5,%6,%7}, {%8,%9}, {%0,%1,%2,%3};"
        : "+f"(c[0]), "+f"(c[1]), "+f"(c[2]), "+f"(c[3])
        : "r"(a[0]), "r"(a[1]), "r"(a[2]), "r"(a[3]), "r"(b0), "r"(b1));
}

__global__ void k_nop() {}

// ---------------- K1: xg = x @ W_ih^T + b_ih via tf32 mma ------------------
// grid (512 m-tiles, 8 n-tiles), 128 threads. 16 k-steps (cols 0..127) mma
// + exact fp32 FMA fixup for col 128. Stride 132 => conflict-free B loads.
__global__ void __launch_bounds__(128) k_xg_t(const float* __restrict__ x,
                                              const float* __restrict__ Wih,
                                              const float* __restrict__ bih) {
    extern __shared__ float sm[];
    float* xs = sm;            // [64][132] tf32 bits (col 128 exact fp32)
    float* ws = sm + 64 * 132; // [64][132]
    const int m0 = blockIdx.x * 64;
    const int g0 = blockIdx.y * 64;
    const int tid = threadIdx.x;

    for (int i = tid; i < 64 * 132; i += 128) {
        int r = i / 132, c = i - r * 132;
        float v = (c < 129) ? x[(size_t)(m0 + r) * 129 + c] : 0.f;
        xs[i] = (c == 128) ? v : __uint_as_float(tf32of(v));
    }
    for (int i = tid; i < 64 * 132; i += 128) {
        int r = i / 132, c = i - r * 132;
        float v = (c < 129) ? Wih[(size_t)(g0 + r) * 129 + c] : 0.f;
        ws[i] = (c == 128) ? v : __uint_as_float(tf32of(v));
    }
    __syncthreads();

    const int warp = tid >> 5, lane = tid & 31;
    const int gid = lane >> 2, tig = lane & 3;
    const int wr = warp * 16;
    const unsigned* xsu = (const unsigned*)xs;
    const unsigned* wsu = (const unsigned*)ws;

    float s[8][4];
#pragma unroll
    for (int n = 0; n < 8; n++) { s[n][0]=0.f; s[n][1]=0.f; s[n][2]=0.f; s[n][3]=0.f; }

#pragma unroll
    for (int kk = 0; kk < 16; kk++) {
        unsigned a[4];
        int cc = kk * 8 + tig;
        a[0] = xsu[(wr + gid)     * 132 + cc];
        a[1] = xsu[(wr + gid + 8) * 132 + cc];
        a[2] = xsu[(wr + gid)     * 132 + cc + 4];
        a[3] = xsu[(wr + gid + 8) * 132 + cc + 4];
#pragma unroll
        for (int n = 0; n < 8; n++) {
            unsigned b0 = wsu[(n * 8 + gid) * 132 + cc];
            unsigned b1 = wsu[(n * 8 + gid) * 132 + cc + 4];
            mma_tf32(s[n], a, b0, b1);
        }
    }

    // k = 128 fixup in exact fp32 (C frag: rows gid,gid+8; cols n*8+2tig,+1)
    float x0 = xs[(wr + gid)     * 132 + 128];
    float x1 = xs[(wr + gid + 8) * 132 + 128];
#pragma unroll
    for (int n = 0; n < 8; n++) {
        float w0 = ws[(n * 8 + 2 * tig)     * 132 + 128];
        float w1 = ws[(n * 8 + 2 * tig + 1) * 132 + 128];
        s[n][0] += x0 * w0; s[n][1] += x0 * w1;
        s[n][2] += x1 * w0; s[n][3] += x1 * w1;
    }

    int r0 = m0 + wr + gid, r1 = r0 + 8;
#pragma unroll
    for (int n = 0; n < 8; n++) {
        int g = g0 + n * 8 + 2 * tig;
        float b0 = bih[g], b1 = bih[g + 1];
        *(float2*)(g_xg + (size_t)r0 * 512 + g) = make_float2(s[n][0] + b0, s[n][1] + b1);
        *(float2*)(g_xg + (size_t)r1 * 512 + g) = make_float2(s[n][2] + b0, s[n][3] + b1);
    }
}

// ---------------- K2: LSTM recurrence — R4 layout, fp16 streamed weights ---
// thread t: j = t>>1; even -> gates (i: j, g: 256+j); odd -> (f: 128+j, o: 384+j)
// 80 weights/gate in fp32 registers; 48/gate streamed from smem as fp16
// (halves crossbar traffic), h double-buffered, ONE barrier per step.
__global__ void __launch_bounds__(256, 1)
k_lstm7(const float* __restrict__ Whh, const float* __restrict__ bhh) {
    extern __shared__ float sm[];
    uint2* wshh = (uint2*)sm;             // 24 slots * 256 threads * uint2 (4 fp16)
    float* hb   = sm + 24 * 256 * 2;      // [2][128] double-buffered h

    const int b = blockIdx.x;
    const int t = threadIdx.x;
    const int j = t >> 1;
    const bool odd = (t & 1);
    const int gA = odd ? (128 + j) : j;
    const int gB = gA + 256;

    const ulonglong2* WA = (const ulonglong2*)(Whh + (size_t)gA * 128);
    const ulonglong2* WB = (const ulonglong2*)(Whh + (size_t)gB * 128);
    ulonglong2 wA[20], wB[20];
#pragma unroll
    for (int k = 0; k < 20; k++) { wA[k] = WA[k]; wB[k] = WB[k]; }
    {
        const float4* WA4 = (const float4*)WA;
        const float4* WB4 = (const float4*)WB;
#pragma unroll
        for (int k = 0; k < 12; k++) {
            float4 wa = WA4[20 + k];
            float4 wb = WB4[20 + k];
            wshh[k * 256 + t]        = make_uint2(f2h2(wa.x, wa.y), f2h2(wa.z, wa.w));
            wshh[(12 + k) * 256 + t] = make_uint2(f2h2(wb.x, wb.y), f2h2(wb.z, wb.w));
        }
    }
    const float bA = bhh[gA], bB = bhh[gB];

    if (t < 128) hb[t] = 0.f;
    float c = 0.f;

    const float* xgp = g_xg + (size_t)b * 2048 * 512;
    float xgA = xgp[gA], xgB = xgp[gB];
    __syncthreads();

    for (int s = 0; s < 2048; s++) {
        float nA = 0.f, nB = 0.f;
        if (s + 1 < 2048) {
            nA = xgp[(size_t)(s + 1) * 512 + gA];
            nB = xgp[(size_t)(s + 1) * 512 + gB];
        }

        const ulonglong2* h2 = (const ulonglong2*)(hb + (s & 1) * 128);
        u64 a0 = 0ull, a1 = 0ull, d0 = 0ull, d1 = 0ull;
#pragma unroll
        for (int k = 0; k < 20; k++) {
            ulonglong2 hv = h2[k];
            fma2(a0, wA[k].x, hv.x); fma2(a1, wA[k].y, hv.y);
            fma2(d0, wB[k].x, hv.x); fma2(d1, wB[k].y, hv.y);
        }
#pragma unroll
        for (int k = 0; k < 12; k++) {
            ulonglong2 hv = h2[20 + k];
            uint2 wa = wshh[k * 256 + t];
            uint2 wb = wshh[(12 + k) * 256 + t];
            fma2(a0, h2f2(wa.x), hv.x); fma2(a1, h2f2(wa.y), hv.y);
            fma2(d0, h2f2(wb.x), hv.x); fma2(d1, h2f2(wb.y), hv.y);
        }
        float a = hsum2(a0) + hsum2(a1);
        float d = hsum2(d0) + hsum2(d1);

        float pre0 = a + xgA + bA;
        float pre1 = d + xgB + bB;
        float q0 = __shfl_xor_sync(0xffffffffu, pre0, 1);
        float q1 = __shfl_xor_sync(0xffffffffu, pre1, 1);
        float ip, fp, gp, op;
        if (!odd) { ip = pre0; gp = pre1; fp = q0;   op = q1;   }
        else      { ip = q0;   gp = q1;   fp = pre0; op = pre1; }

        c = sigf(fp) * c + sigf(ip) * tanh_fast(gp);
        float h = sigf(op) * tanh_fast(c);

        float* hn = hb + ((s + 1) & 1) * 128;
        if (!odd) {
            hn[j] = h;
            g_lstm[((size_t)b * 2048 + s) * 128 + j] = h;
        }
        xgA = nA; xgB = nB;
        __syncthreads();
    }
}

// ---------------- K3: flash attention, tf32 mma.sync — PROVEN (R4) ---------
__global__ void __launch_bounds__(128) k_attn() {
    extern __shared__ float sm[];
    float* qs = sm;                 // [64][132] tf32 bits of q * 1/sqrt(129)
    float* ks = sm + 64 * 132;      // [64][132] tf32 bits of K==V chunk
    float* ps = ks + 64 * 132;      // [64][68]  tf32 probs

    const int b  = blockIdx.y;
    const int r0 = blockIdx.x * 64;
    const float* base = g_lstm + (size_t)b * 2048 * 128;
    const int tid  = threadIdx.x;
    const int warp = tid >> 5, lane = tid & 31;
    const int gid  = lane >> 2, tig = lane & 3;
    const int wr   = warp * 16;
    const float rs = 0.08804509063256238f; // 1/sqrt(129)

    {   // stage q tile: scale + tf32-round
        const float4* qg = (const float4*)(base + (size_t)r0 * 128);
        float4* qs4 = (float4*)qs;
        for (int i = tid; i < 2048; i += 128) {
            int row = i >> 5, c = i & 31;
            float4 v = qg[row * 32 + c];
            v.x = __uint_as_float(tf32of(v.x * rs));
            v.y = __uint_as_float(tf32of(v.y * rs));
            v.z = __uint_as_float(tf32of(v.z * rs));
            v.w = __uint_as_float(tf32of(v.w * rs));
            qs4[row * 33 + c] = v;
        }
    }

    float m0 = -1e30f, m1 = -1e30f, l0 = 0.f, l1 = 0.f;
    float o[16][4];
#pragma unroll
    for (int n = 0; n < 16; n++) { o[n][0]=0.f; o[n][1]=0.f; o[n][2]=0.f; o[n][3]=0.f; }

    const unsigned* qsu = (const unsigned*)qs;
    const unsigned* ksu = (const unsigned*)ks;

    for (int kt = 0; kt < 32; kt++) {
        __syncthreads();
        {   // stage K/V chunk as tf32
            const float4* kg = (const float4*)(base + (size_t)kt * 64 * 128);
            float4* ks4 = (float4*)ks;
            for (int i = tid; i < 2048; i += 128) {
                int row = i >> 5, c = i & 31;
                float4 v = kg[row * 32 + c];
                v.x = __uint_as_float(tf32of(v.x));
                v.y = __uint_as_float(tf32of(v.y));
                v.z = __uint_as_float(tf32of(v.z));
                v.w = __uint_as_float(tf32of(v.w));
                ks4[row * 33 + c] = v;
            }
        }
        __syncthreads();

        // phase 1: S(16x64) = Q @ K^T
        float s[8][4];
#pragma unroll
        for (int n = 0; n < 8; n++) { s[n][0]=0.f; s[n][1]=0.f; s[n][2]=0.f; s[n][3]=0.f; }
#pragma unroll
        for (int kk = 0; kk < 16; kk++) {
            unsigned a[4];
            int cc = kk * 8 + tig;
            a[0] = qsu[(wr + gid)     * 132 + cc];
            a[1] = qsu[(wr + gid + 8) * 132 + cc];
            a[2] = qsu[(wr + gid)     * 132 + cc + 4];
            a[3] = qsu[(wr + gid + 8) * 132 + cc + 4];
#pragma unroll
            for (int n = 0; n < 8; n++) {
                unsigned b0 = ksu[(n * 8 + gid) * 132 + cc];
                unsigned b1 = ksu[(n * 8 + gid) * 132 + cc + 4];
                mma_tf32(s[n], a, b0, b1);
            }
        }

        // online softmax
        float vm0 = -1e30f, vm1 = -1e30f;
#pragma unroll
        for (int n = 0; n < 8; n++) {
            vm0 = fmaxf(vm0, fmaxf(s[n][0], s[n][1]));
            vm1 = fmaxf(vm1, fmaxf(s[n][2], s[n][3]));
        }
        vm0 = fmaxf(vm0, __shfl_xor_sync(0xffffffffu, vm0, 1));
        vm0 = fmaxf(vm0, __shfl_xor_sync(0xffffffffu, vm0, 2));
        vm1 = fmaxf(vm1, __shfl_xor_sync(0xffffffffu, vm1, 1));
        vm1 = fmaxf(vm1, __shfl_xor_sync(0xffffffffu, vm1, 2));
        float nm0 = fmaxf(m0, vm0), nm1 = fmaxf(m1, vm1);

        float sum0 = 0.f, sum1 = 0.f;
#pragma unroll
        for (int n = 0; n < 8; n++) {
            float p0 = __expf(s[n][0] - nm0);
            float p1 = __expf(s[n][1] - nm0);
            float p2 = __expf(s[n][2] - nm1);
            float p3 = __expf(s[n][3] - nm1);
            sum0 += p0 + p1; sum1 += p2 + p3;
            float* pp = ps + (wr + gid) * 68 + n * 8 + 2 * tig;
            pp[0] = __uint_as_float(tf32of(p0));
            pp[1] = __uint_as_float(tf32of(p1));
            float* pq = ps + (wr + gid + 8) * 68 + n * 8 + 2 * tig;
            pq[0] = __uint_as_float(tf32of(p2));
            pq[1] = __uint_as_float(tf32of(p3));
        }
        sum0 += __shfl_xor_sync(0xffffffffu, sum0, 1);
        sum0 += __shfl_xor_sync(0xffffffffu, sum0, 2);
        sum1 += __shfl_xor_sync(0xffffffffu, sum1, 1);
        sum1 += __shfl_xor_sync(0xffffffffu, sum1, 2);
        float alpha0 = __expf(m0 - nm0), alpha1 = __expf(m1 - nm1);
        l0 = l0 * alpha0 + sum0; m0 = nm0;
        l1 = l1 * alpha1 + sum1; m1 = nm1;
        __syncwarp();

        // phase 2: O(16x128) += P @ V
#pragma unroll
        for (int n = 0; n < 16; n++) {
            o[n][0] *= alpha0; o[n][1] *= alpha0;
            o[n][2] *= alpha1; o[n][3] *= alpha1;
        }
        const unsigned* psu = (const unsigned*)ps;
#pragma unroll
        for (int kk = 0; kk < 8; kk++) {
            unsigned pa[4];
            pa[0] = psu[(wr + gid)     * 68 + kk * 8 + tig];
            pa[1] = psu[(wr + gid + 8) * 68 + kk * 8 + tig];
            pa[2] = psu[(wr + gid)     * 68 + kk * 8 + tig + 4];
            pa[3] = psu[(wr + gid + 8) * 68 + kk * 8 + tig + 4];
#pragma unroll
            for (int n = 0; n < 16; n++) {
                unsigned b0 = ksu[(kk * 8 + tig)     * 132 + n * 8 + gid];
                unsigned b1 = ksu[(kk * 8 + tig + 4) * 132 + n * 8 + gid];
                mma_tf32(o[n], pa, b0, b1);
            }
        }
    }

    // epilogue
    float inv0 = 1.f / l0, inv1 = 1.f / l1;
    int row0 = r0 + wr + gid, row1 = row0 + 8;
    float* d0 = g_ctx + ((size_t)b * 2048 + row0) * 128;
    float* d1 = g_ctx + ((size_t)b * 2048 + row1) * 128;
#pragma unroll
    for (int n = 0; n < 16; n++) {
        int cc = n * 8 + 2 * tig;
        *(float2*)(d0 + cc) = make_float2(o[n][0] * inv0, o[n][1] * inv0);
        *(float2*)(d1 + cc) = make_float2(o[n][2] * inv1, o[n][3] * inv1);
    }
}

// ---------------- K4: concat(context, RBF kernel feature), pad to 132 ------
__global__ void k_feat(const float* __restrict__ x, const float* __restrict__ pr) {
    const int tid = threadIdx.x;
    const int warp = tid >> 5, lane = tid & 31;
    const size_t mrow = (size_t)blockIdx.x * 8 + warp;

    const float4* c4 = (const float4*)(g_ctx + mrow * 128);
    float4* o4 = (float4*)(g_ha + mrow * 132);
    o4[lane] = c4[lane];

    const float* xr = x  + mrow * 129;
    const float* pp = pr + mrow * 129;
    float ss = 0.f;
    for (int j2 = lane; j2 < 129; j2 += 32) {
        float d = xr[j2] - pp[j2];
        ss += d * d;
    }
#pragma unroll
    for (int dd = 16; dd; dd >>= 1) ss += __shfl_xor_sync(0xffffffffu, ss, dd);
    if (lane == 0)      g_ha[mrow * 132 + 128] = __expf(-ss);
    else if (lane < 4)  g_ha[mrow * 132 + 128 + lane] = 0.f;
}

// ---------------- K5: one MLP layer h = relu(h @ Wc[l]^T + bc[l]) — PROVEN -
__global__ void k_mlp(const float* __restrict__ Wc, const float* __restrict__ bc, int l) {
    extern __shared__ float sm[];
    float* Wsh  = sm;              // [132][134]
    float* insh = sm + 132 * 134;  // [64][132]
    const float* in  = (l & 1) ? g_hb : g_ha;
    float*       out = (l & 1) ? g_ha : g_hb;

    const int m0 = blockIdx.x * 64;
    const int tid = threadIdx.x;
    const float* W  = Wc + (size_t)l * 129 * 129;
    const float* bb = bc + (size_t)l * 129;

    for (int i = tid; i < 132 * 134; i += 256) {
        int r = i / 134, c = i - r * 134;
        Wsh[i] = (r < 129 && c < 129) ? W[r * 129 + c] : 0.f;
    }
    for (int i = tid; i < 64 * 132; i += 256)
        insh[i] = in[(size_t)m0 * 132 + i];
    __syncthreads();

    const int warp = tid >> 5, lane = tid & 31;
    const int rb = warp * 8;
    const u64* W2 = (const u64*)Wsh;   // row stride 67 pairs

#pragma unroll
    for (int q = 0; q < 2; q++) {
        u64 acc2[4][5] = {};
        const int r0 = rb + 4 * q;
        const u64* h0p = (const u64*)(insh + (r0 + 0) * 132);
        const u64* h1p = (const u64*)(insh + (r0 + 1) * 132);
        const u64* h2p = (const u64*)(insh + (r0 + 2) * 132);
        const u64* h3p = (const u64*)(insh + (r0 + 3) * 132);
#pragma unroll 2
        for (int jp = 0; jp < 66; jp++) {
            u64 h0 = h0p[jp], h1 = h1p[jp], h2 = h2p[jp], h3 = h3p[jp];
#pragma unroll
            for (int cg = 0; cg < 5; cg++) {
                int cc = lane + 32 * cg;
                if (cc < 132) {
                    u64 w = W2[cc * 67 + jp];
                    fma2(acc2[0][cg], h0, w); fma2(acc2[1][cg], h1, w);
                    fma2(acc2[2][cg], h2, w); fma2(acc2[3][cg], h3, w);
                }
            }
        }
#pragma unroll
        for (int cg = 0; cg < 5; cg++) {
            int cc = lane + 32 * cg;
            if (cc < 132) {
                float bv = (cc < 129) ? bb[cc] : 0.f;
#pragma unroll
                for (int i = 0; i < 4; i++)
                    out[(size_t)(m0 + rb + 4 * q + i) * 132 + cc] =
                        fmaxf(hsum2(acc2[i][cg]) + bv, 0.f);
            }
        }
    }
}

// ---------------- K6: head + log_softmax -----------------------------------
__global__ void k_head(const float* __restrict__ Wh, const float* __restrict__ bh,
                       float* __restrict__ out) {
    const int tid = threadIdx.x;
    const int warp = tid >> 5, lane = tid & 31;
    const size_t mrow = (size_t)blockIdx.x * 8 + warp;
    const float* hr = g_ha + mrow * 132;

    float s0 = 0.f, s1 = 0.f;
    for (int j2 = lane; j2 < 129; j2 += 32) {
        float hv = hr[j2];
        s0 += hv * Wh[j2];
        s1 += hv * Wh[129 + j2];
    }
#pragma unroll
    for (int dd = 16; dd; dd >>= 1) {
        s0 += __shfl_xor_sync(0xffffffffu, s0, dd);
        s1 += __shfl_xor_sync(0xffffffffu, s1, dd);
    }
    if (lane == 0) {
        s0 += bh[0]; s1 += bh[1];
        float mx = fmaxf(s0, s1);
        float lse = mx + logf(__expf(s0 - mx) + __expf(s1 - mx));
        out[2 * mrow]     = s0 - lse;
        out[2 * mrow + 1] = s1 - lse;
    }
}

// ---------------- launch ---------------------------------------------------
extern "C" void kernel_launch(void* const* d_in, const int* in_sizes, int n_in,
                              void* d_out, int out_size) {
    const float* x     = (const float*)d_in[0];
    const float* proto = (const float*)d_in[1];
    const float* Wih   = (const float*)d_in[2];
    const float* Whh   = (const float*)d_in[3];
    const float* bih   = (const float*)d_in[4];
    const float* bhh   = (const float*)d_in[5];
    const float* Wc    = (const float*)d_in[6];
    const float* bc    = (const float*)d_in[7];
    const float* Wh    = (const float*)d_in[8];
    const float* bh    = (const float*)d_in[9];
    float* out = (float*)d_out;

    const int smem_xg   = 2 * 64 * 132 * 4;                 // 67584
    const int smem_lstm = 24 * 256 * 8 + 2 * 128 * 4;       // 50176
    const int smem_attn = (2 * 64 * 132 + 64 * 68) * 4;     // 84992
    const int smem_mlp  = (132 * 134 + 64 * 132) * 4;       // 104544

    cudaFuncSetAttribute(k_xg_t,  cudaFuncAttributeMaxDynamicSharedMemorySize, smem_xg);
    cudaFuncSetAttribute(k_lstm7, cudaFuncAttributeMaxDynamicSharedMemorySize, smem_lstm);
    cudaFuncSetAttribute(k_attn,  cudaFuncAttributeMaxDynamicSharedMemorySize, smem_attn);
    cudaFuncSetAttribute(k_mlp,   cudaFuncAttributeMaxDynamicSharedMemorySize, smem_mlp);

    k_xg_t<<<dim3(512, 8), 128, smem_xg>>>(x, Wih, bih);
    k_nop <<<1, 32>>>();          // shift ncu slot:
    k_nop <<<1, 32>>>();          // ... so launch #4 is k_lstm7
    k_lstm7<<<16, 256, smem_lstm>>>(Whh, bhh);
    k_attn<<<dim3(32, 16), 128, smem_attn>>>();
    k_feat<<<4096,         256>>>(x, proto);
    for (int l = 0; l < 4; l++)
        k_mlp<<<512, 256, smem_mlp>>>(Wc, bc, l);
    k_head<<<4096, 256>>>(Wh, bh, out);
}